// round 6
// baseline (speedup 1.0000x reference)
#include <cuda_runtime.h>
#include <cuda_bf16.h>
#include <cstdint>
#include <cstddef>

// Problem constants
#define NROWS   65536
#define VDIM    1024
#define DDIM    256
#define M_TILE  64
#define NCTAS   (NROWS / M_TILE)     // 1024
#define NTHREADS 384                 // 256 consumers + 128 producers
#define NCONS   256
#define KCH     64
#define NCHUNK  (VDIM / KCH)         // 16
#define NSTAGE  3
#define ROWB    144                  // bytes per smem tile row (64 bf16 + 8 pad)
#define A_TILE  (M_TILE * ROWB)      // 9216
#define B_TILE  (DDIM * ROWB)        // 36864
#define SMEM_DYN (NSTAGE * (A_TILE + B_TILE))   // 138240

// Static scratch: codebook transposed+converted to bf16, [D][V]
__device__ __nv_bfloat16 g_cbT[DDIM * VDIM];
__device__ int g_tgt64;

// ---------------------------------------------------------------------------
// Prep: transpose codebook fp32 [V][D] -> bf16 [D][V]; zero out; dtype sniff.
// ---------------------------------------------------------------------------
__global__ void prep_kernel(const float* __restrict__ cb,
                            const void*  __restrict__ tgt,
                            float* __restrict__ out) {
    __shared__ float tile[32][33];
    int v0 = blockIdx.x * 32;
    int d0 = blockIdx.y * 32;
    int tx = threadIdx.x, ty = threadIdx.y;

    #pragma unroll
    for (int i = 0; i < 4; i++) {
        int v = ty + i * 8;
        tile[v][tx] = cb[(size_t)(v0 + v) * DDIM + d0 + tx];
    }
    __syncthreads();
    #pragma unroll
    for (int i = 0; i < 4; i++) {
        int d = ty + i * 8;
        g_cbT[(size_t)(d0 + d) * VDIM + v0 + tx] = __float2bfloat16(tile[tx][d]);
    }

    if (blockIdx.x == 0 && blockIdx.y == 0 && tx == 0 && ty == 0) {
        const int* t = (const int*)tgt;
        int is64 = 1;
        for (int i = 0; i < 256; i++) {
            if (t[2 * i + 1] != 0) { is64 = 0; break; }
        }
        g_tgt64 = is64;
        out[0] = 0.0f;
    }
}

// ---------------------------------------------------------------------------
// Helpers
// ---------------------------------------------------------------------------
__device__ __forceinline__ uint32_t smem_u32(const void* p) {
    uint32_t a;
    asm("{ .reg .u64 t; cvta.to.shared.u64 t, %1; cvt.u32.u64 %0, t; }" : "=r"(a) : "l"(p));
    return a;
}

__device__ __forceinline__ void cp16(uint32_t dst_smem, const void* src_gmem) {
    asm volatile("cp.async.cg.shared.global [%0], [%1], 16;" :: "r"(dst_smem), "l"(src_gmem));
}

__device__ __forceinline__ void ldsm_x4(uint32_t (&r)[4], uint32_t addr) {
    asm volatile("ldmatrix.sync.aligned.m8n8.x4.shared.b16 {%0,%1,%2,%3}, [%4];"
                 : "=r"(r[0]), "=r"(r[1]), "=r"(r[2]), "=r"(r[3]) : "r"(addr));
}

__device__ __forceinline__ void mma16816(float (&c)[4], const uint32_t (&a)[4],
                                         uint32_t b0, uint32_t b1) {
    asm volatile(
        "mma.sync.aligned.m16n8k16.row.col.f32.bf16.bf16.f32 "
        "{%0,%1,%2,%3}, {%4,%5,%6,%7}, {%8,%9}, {%0,%1,%2,%3};"
        : "+f"(c[0]), "+f"(c[1]), "+f"(c[2]), "+f"(c[3])
        : "r"(a[0]), "r"(a[1]), "r"(a[2]), "r"(a[3]), "r"(b0), "r"(b1));
}

__device__ __forceinline__ void mbar_wait(uint32_t mbar, uint32_t parity) {
    uint32_t done;
    asm volatile(
        "{\n\t.reg .pred p;\n\t"
        "mbarrier.try_wait.parity.acquire.cta.shared::cta.b64 p, [%1], %2;\n\t"
        "selp.b32 %0, 1, 0, p;\n\t}"
        : "=r"(done) : "r"(mbar), "r"(parity) : "memory");
    if (!done) {
        asm volatile(
            "{\n\t.reg .pred P1;\n\t"
            "W_%=:\n\t"
            "mbarrier.try_wait.parity.acquire.cta.shared::cta.b64 P1, [%0], %1, 0x989680;\n\t"
            "@P1 bra.uni D_%=;\n\t"
            "bra.uni W_%=;\n\t"
            "D_%=:\n\t}"
            :: "r"(mbar), "r"(parity) : "memory");
    }
}

__device__ __forceinline__ void mbar_arrive(uint32_t mbar) {
    asm volatile("mbarrier.arrive.shared.b64 _, [%0];" :: "r"(mbar) : "memory");
}

// ---------------------------------------------------------------------------
// Warp-specialized fused kernel.
// Warps 0-7 (256 thr): consumers — LDSM + mma.sync, acc in regs.
// Warps 8-11 (128 thr): producers — logits LDG -> exp -> A STS; B cp.async.
// 3-stage A/B ring gated by full/empty mbarriers.
// ---------------------------------------------------------------------------
__global__ void __launch_bounds__(NTHREADS, 1)
loss_kernel(const float* __restrict__ logits,
            const void*  __restrict__ tgt,
            const float* __restrict__ cb,
            float* __restrict__ out) {
    extern __shared__ char smem[];
    char* Atiles = smem;                      // [3][64][144B]
    char* Btiles = smem + NSTAGE * A_TILE;    // [3][256][144B]
    __shared__ float rowinv[M_TILE];
    __shared__ float sred[8];
    __shared__ __align__(8) unsigned long long mbar[2 * NSTAGE];  // full[3], empty[3]

    const int tid = threadIdx.x;
    const uint32_t a_smem = smem_u32(Atiles);
    const uint32_t b_smem = smem_u32(Btiles);
    const uint32_t mb_full  = smem_u32(&mbar[0]);
    const uint32_t mb_empty = smem_u32(&mbar[NSTAGE]);

    if (tid == 0) {
        #pragma unroll
        for (int s = 0; s < NSTAGE; s++) {
            asm volatile("mbarrier.init.shared.b64 [%0], %1;"
                         :: "r"(mb_full + s * 8), "r"(128u) : "memory");
            asm volatile("mbarrier.init.shared.b64 [%0], %1;"
                         :: "r"(mb_empty + s * 8), "r"(256u) : "memory");
        }
    }
    __syncthreads();

    if (tid < NCONS) {
        // ------------------------- CONSUMERS -------------------------------
        const int lane = tid & 31;
        const int wid  = tid >> 5;
        const int warp_m = wid & 1;
        const int warp_n = wid >> 1;

        // ldmatrix offsets (within a stage)
        const uint32_t a_lds_off =
            (uint32_t)((warp_m * 32 + (lane & 15)) * ROWB + ((lane >> 4) << 4));
        const uint32_t b_lds_off =
            (uint32_t)(((lane & 7) + ((lane >> 4) << 3)) * ROWB + (((lane >> 3) & 1) << 4));

        float acc[2][8][4];
        #pragma unroll
        for (int mi = 0; mi < 2; mi++)
            #pragma unroll
            for (int nf = 0; nf < 8; nf++)
                #pragma unroll
                for (int x = 0; x < 4; x++) acc[mi][nf][x] = 0.0f;

        int s = 0, u = 0;
        #pragma unroll 1
        for (int kc = 0; kc < NCHUNK; kc++) {
            mbar_wait(mb_full + s * 8, (uint32_t)(u & 1));

            const uint32_t a_buf = a_smem + s * A_TILE + a_lds_off;
            const uint32_t b_buf = b_smem + s * B_TILE + b_lds_off;

            #pragma unroll
            for (int ks = 0; ks < 4; ks++) {
                uint32_t afr[2][4];
                ldsm_x4(afr[0], a_buf + ks * 32);
                ldsm_x4(afr[1], a_buf + 16 * ROWB + ks * 32);
                #pragma unroll
                for (int nb = 0; nb < 4; nb++) {
                    uint32_t bfr[4];
                    ldsm_x4(bfr, b_buf + (warp_n * 64 + nb * 16) * ROWB + ks * 32);
                    mma16816(acc[0][nb * 2 + 0], afr[0], bfr[0], bfr[1]);
                    mma16816(acc[0][nb * 2 + 1], afr[0], bfr[2], bfr[3]);
                    mma16816(acc[1][nb * 2 + 0], afr[1], bfr[0], bfr[1]);
                    mma16816(acc[1][nb * 2 + 1], afr[1], bfr[2], bfr[3]);
                }
            }
            mbar_arrive(mb_empty + s * 8);

            if (++s == NSTAGE) { s = 0; u++; }
        }

        __syncthreads();   // producers have published rowinv

        // Epilogue: pred = acc * rowinv; loss += (pred - cb[target])^2
        const int is64 = g_tgt64;
        const long long* t64 = (const long long*)tgt;
        const int*       t32 = (const int*)tgt;

        float lsum = 0.0f;
        #pragma unroll
        for (int mi = 0; mi < 2; mi++) {
            int lr0 = warp_m * 32 + mi * 16 + (lane >> 2);
            int lr1 = lr0 + 8;
            int r0 = blockIdx.x * M_TILE + lr0;
            int r1 = blockIdx.x * M_TILE + lr1;
            float inv0 = rowinv[lr0];
            float inv1 = rowinv[lr1];
            int tg0 = is64 ? (int)t64[r0] : t32[r0];
            int tg1 = is64 ? (int)t64[r1] : t32[r1];
            const float* cb0 = cb + (size_t)tg0 * DDIM;
            const float* cb1 = cb + (size_t)tg1 * DDIM;
            #pragma unroll
            for (int nf = 0; nf < 8; nf++) {
                int col = warp_n * 64 + nf * 8 + (lane & 3) * 2;
                float2 g0 = *(const float2*)(cb0 + col);
                float2 g1 = *(const float2*)(cb1 + col);
                float d0 = acc[mi][nf][0] * inv0 - g0.x;
                float d1 = acc[mi][nf][1] * inv0 - g0.y;
                float d2 = acc[mi][nf][2] * inv1 - g1.x;
                float d3 = acc[mi][nf][3] * inv1 - g1.y;
                lsum += d0 * d0 + d1 * d1 + d2 * d2 + d3 * d3;
            }
        }
        #pragma unroll
        for (int off = 16; off > 0; off >>= 1)
            lsum += __shfl_xor_sync(0xffffffffu, lsum, off);
        if (lane == 0) sred[wid] = lsum;
    } else {
        // ------------------------- PRODUCERS -------------------------------
        const int p    = tid - NCONS;       // 0..127
        const int row  = p >> 1;            // 0..63
        const int half = p & 1;             // k-half within chunk

        const float4* src4 = (const float4*)(logits + (size_t)blockIdx.x * M_TILE * VDIM);
        const size_t rb4 = (size_t)row * (VDIM / 4);

        float4 cur[8], nxt[8];
        #pragma unroll
        for (int j = 0; j < 8; j++)
            cur[j] = src4[rb4 + half * 8 + j];

        float rs = 0.0f;
        int s = 0, u = 0;

        #pragma unroll 1
        for (int kc = 0; kc < NCHUNK; kc++) {
            // Prefetch next logits chunk (regs; independent of barrier).
            if (kc + 1 < NCHUNK) {
                #pragma unroll
                for (int j = 0; j < 8; j++)
                    nxt[j] = src4[rb4 + (kc + 1) * 16 + half * 8 + j];
            }

            // Wait for the stage to be free (first pass of each slot is free).
            mbar_wait(mb_empty + s * 8, (uint32_t)((u + 1) & 1));

            // B cp.async first (latency overlapped with exp below).
            uint32_t bdst = b_smem + s * B_TILE;
            #pragma unroll
            for (int i = 0; i < 16; i++) {
                int idx = p + i * 128;       // 0..2047
                int n   = idx >> 3;
                int kv  = idx & 7;
                cp16(bdst + n * ROWB + kv * 16,
                     g_cbT + (size_t)n * VDIM + kc * KCH + kv * 8);
            }
            asm volatile("cp.async.commit_group;" ::: "memory");

            // exp + rowsum + bf16 store: 32 values -> 4 x 16B into A[s].
            char* adst = Atiles + s * A_TILE + row * ROWB + half * 64;
            #pragma unroll
            for (int i = 0; i < 4; i++) {
                float4 v0 = cur[2 * i];
                float4 v1 = cur[2 * i + 1];
                float e0 = __expf(v0.x), e1 = __expf(v0.y);
                float e2 = __expf(v0.z), e3 = __expf(v0.w);
                float e4 = __expf(v1.x), e5 = __expf(v1.y);
                float e6 = __expf(v1.z), e7 = __expf(v1.w);
                rs += ((e0 + e1) + (e2 + e3)) + ((e4 + e5) + (e6 + e7));
                __nv_bfloat162 h0 = __floats2bfloat162_rn(e0, e1);
                __nv_bfloat162 h1 = __floats2bfloat162_rn(e2, e3);
                __nv_bfloat162 h2 = __floats2bfloat162_rn(e4, e5);
                __nv_bfloat162 h3 = __floats2bfloat162_rn(e6, e7);
                uint4 pk;
                pk.x = *(unsigned*)&h0;
                pk.y = *(unsigned*)&h1;
                pk.z = *(unsigned*)&h2;
                pk.w = *(unsigned*)&h3;
                *(uint4*)(adst + i * 16) = pk;
            }

            // Our B copies done -> stage complete for our share; publish.
            asm volatile("cp.async.wait_group 0;" ::: "memory");
            mbar_arrive(mb_full + s * 8);

            #pragma unroll
            for (int j = 0; j < 8; j++) cur[j] = nxt[j];
            if (++s == NSTAGE) { s = 0; u++; }
        }

        // Row sums: pair (p, p^1) share a row (adjacent lanes).
        float ssum = rs + __shfl_xor_sync(0xffffffffu, rs, 1);
        if (half == 0) rowinv[row] = 1.0f / ssum;

        __syncthreads();   // matches consumers' pre-epilogue sync
    }

    __syncthreads();       // sred visible
    if (tid == 0) {
        float tot = 0.0f;
        #pragma unroll
        for (int i = 0; i < 8; i++) tot += sred[i];
        atomicAdd(out, tot * (1.0f / ((float)NROWS * (float)DDIM)));
    }
}

// ---------------------------------------------------------------------------
// Launch
// ---------------------------------------------------------------------------
extern "C" void kernel_launch(void* const* d_in, const int* in_sizes, int n_in,
                              void* d_out, int out_size) {
    const float* logits = nullptr;
    const void*  tgt    = nullptr;
    const float* cb     = nullptr;
    for (int i = 0; i < n_in; i++) {
        if (in_sizes[i] == NROWS * VDIM)      logits = (const float*)d_in[i];
        else if (in_sizes[i] == NROWS)        tgt    = d_in[i];
        else if (in_sizes[i] == VDIM * DDIM)  cb     = (const float*)d_in[i];
    }
    float* out = (float*)d_out;

    cudaFuncSetAttribute(loss_kernel,
                         cudaFuncAttributeMaxDynamicSharedMemorySize, SMEM_DYN);

    dim3 pgrid(VDIM / 32, DDIM / 32);
    dim3 pblk(32, 8);
    prep_kernel<<<pgrid, pblk>>>(cb, tgt, out);

    loss_kernel<<<NCTAS, NTHREADS, SMEM_DYN>>>(logits, tgt, cb, out);
}